// round 1
// baseline (speedup 1.0000x reference)
#include <cuda_runtime.h>
#include <math.h>

#define B_   2
#define L_   2048
#define DM   768
#define DI   1536
#define DS   16
#define DR   48
#define XZW  (2*DI)        /* 3072 */
#define SSW  (DR + 2*DS)   /* 80   */
#define ML   (B_*L_)       /* 4096 */

// ---------------- scratch (static device globals; no allocation) -------------
__device__ float g_xz [ML * XZW];   // xz = x @ W_in          [4096,3072]
__device__ float g_u  [ML * DI];    // conv+silu output       [4096,1536]
__device__ float g_ssm[ML * SSW];   // u @ W_x                [4096,80]
__device__ float g_dt [ML * DI];    // softplus(dt_raw@W_dt+b)[4096,1536]
__device__ float g_y  [ML * DI];    // scan output (pre W_out)[4096,1536]

// =====================================================================
// 128x128x8 fp32 GEMM, 256 threads, 8x8 per thread (4+4 split).
// Requires M%128==0, N%128==0, K%8==0, contiguous row-major (lda=K, ldb=ldc=N).
// =====================================================================
__global__ __launch_bounds__(256) void gemm128(
    const float* __restrict__ A, const float* __restrict__ Bm,
    float* __restrict__ C, int M, int N, int K)
{
    __shared__ float As[8][128];
    __shared__ float Bs[8][128];

    const int tid  = threadIdx.x;
    const int tx   = tid & 15;        // 0..15 -> col groups
    const int ty   = tid >> 4;        // 0..15 -> row groups
    const int row0 = blockIdx.y * 128;
    const int col0 = blockIdx.x * 128;

    const int a_row = tid >> 1;            // 0..127
    const int a_k   = (tid & 1) * 4;       // 0 or 4
    const int b_k   = tid >> 5;            // 0..7
    const int b_c   = (tid & 31) * 4;      // 0..124

    const float* Ag = A  + (size_t)(row0 + a_row) * K + a_k;
    const float* Bg = Bm + (size_t)b_k * N + col0 + b_c;

    float4 a_ld = *(const float4*)Ag;
    float4 b_ld = *(const float4*)Bg;

    float acc[8][8];
#pragma unroll
    for (int i = 0; i < 8; i++)
#pragma unroll
        for (int j = 0; j < 8; j++) acc[i][j] = 0.f;

    for (int k0 = 8; k0 <= K; k0 += 8) {
        As[a_k + 0][a_row] = a_ld.x;
        As[a_k + 1][a_row] = a_ld.y;
        As[a_k + 2][a_row] = a_ld.z;
        As[a_k + 3][a_row] = a_ld.w;
        *(float4*)&Bs[b_k][b_c] = b_ld;
        __syncthreads();

        if (k0 < K) {                      // prefetch next tile
            a_ld = *(const float4*)(Ag + k0);
            b_ld = *(const float4*)(Bg + (size_t)k0 * N);
        }

#pragma unroll
        for (int k = 0; k < 8; k++) {
            float4 a0 = *(float4*)&As[k][ty * 4];
            float4 a1 = *(float4*)&As[k][64 + ty * 4];
            float4 b0 = *(float4*)&Bs[k][tx * 4];
            float4 b1 = *(float4*)&Bs[k][64 + tx * 4];
            float av[8] = {a0.x, a0.y, a0.z, a0.w, a1.x, a1.y, a1.z, a1.w};
            float bv[8] = {b0.x, b0.y, b0.z, b0.w, b1.x, b1.y, b1.z, b1.w};
#pragma unroll
            for (int i = 0; i < 8; i++)
#pragma unroll
                for (int j = 0; j < 8; j++)
                    acc[i][j] = fmaf(av[i], bv[j], acc[i][j]);
        }
        __syncthreads();
    }

#pragma unroll
    for (int ih = 0; ih < 2; ih++)
#pragma unroll
        for (int i = 0; i < 4; i++) {
            int r = row0 + ih * 64 + ty * 4 + i;
            float4 v0 = make_float4(acc[ih*4+i][0], acc[ih*4+i][1],
                                    acc[ih*4+i][2], acc[ih*4+i][3]);
            float4 v1 = make_float4(acc[ih*4+i][4], acc[ih*4+i][5],
                                    acc[ih*4+i][6], acc[ih*4+i][7]);
            *(float4*)&C[(size_t)r * N + col0 + tx * 4]      = v0;
            *(float4*)&C[(size_t)r * N + col0 + 64 + tx * 4] = v1;
        }
}

// =====================================================================
// 64x64x16 fp32 GEMM with strides, N-guards, optional bias + softplus.
// Requires M%64==0, K%16==0. N arbitrary.
// =====================================================================
__global__ __launch_bounds__(256) void gemm64(
    const float* __restrict__ A, const float* __restrict__ Bm,
    float* __restrict__ C, int M, int N, int K,
    int lda, int ldb, int ldc,
    const float* __restrict__ bias, int do_softplus)
{
    __shared__ float As[16][64];
    __shared__ float Bs[16][64];

    const int tid  = threadIdx.x;
    const int tx   = tid & 15;
    const int ty   = tid >> 4;
    const int row0 = blockIdx.y * 64;
    const int col0 = blockIdx.x * 64;

    const int a_row = tid >> 2;           // 0..63
    const int a_k   = (tid & 3) * 4;      // 0..12
    const int b_k   = tid >> 4;           // 0..15
    const int b_c   = (tid & 15) * 4;     // 0..60

    float acc[4][4];
#pragma unroll
    for (int i = 0; i < 4; i++)
#pragma unroll
        for (int j = 0; j < 4; j++) acc[i][j] = 0.f;

    float4 a_ld, b_ld;
    // initial loads
    a_ld = *(const float4*)(A + (size_t)(row0 + a_row) * lda + a_k);
    if (col0 + b_c + 4 <= N)
        b_ld = *(const float4*)(Bm + (size_t)b_k * ldb + col0 + b_c);
    else
        b_ld = make_float4(0.f, 0.f, 0.f, 0.f);

    for (int k0 = 16; k0 <= K; k0 += 16) {
        As[a_k + 0][a_row] = a_ld.x;
        As[a_k + 1][a_row] = a_ld.y;
        As[a_k + 2][a_row] = a_ld.z;
        As[a_k + 3][a_row] = a_ld.w;
        *(float4*)&Bs[b_k][b_c] = b_ld;
        __syncthreads();

        if (k0 < K) {
            a_ld = *(const float4*)(A + (size_t)(row0 + a_row) * lda + k0 + a_k);
            if (col0 + b_c + 4 <= N)
                b_ld = *(const float4*)(Bm + (size_t)(k0 + b_k) * ldb + col0 + b_c);
            else
                b_ld = make_float4(0.f, 0.f, 0.f, 0.f);
        }

#pragma unroll
        for (int k = 0; k < 16; k++) {
            float4 a = *(float4*)&As[k][ty * 4];
            float4 b = *(float4*)&Bs[k][tx * 4];
            float av[4] = {a.x, a.y, a.z, a.w};
            float bv[4] = {b.x, b.y, b.z, b.w};
#pragma unroll
            for (int i = 0; i < 4; i++)
#pragma unroll
                for (int j = 0; j < 4; j++)
                    acc[i][j] = fmaf(av[i], bv[j], acc[i][j]);
        }
        __syncthreads();
    }

#pragma unroll
    for (int i = 0; i < 4; i++) {
        int r = row0 + ty * 4 + i;
#pragma unroll
        for (int j = 0; j < 4; j++) {
            int c = col0 + tx * 4 + j;
            if (c < N) {
                float v = acc[i][j];
                if (bias) v += bias[c];
                if (do_softplus) v = (v > 20.f) ? v : log1pf(expf(v));
                C[(size_t)r * ldc + c] = v;
            }
        }
    }
}

// =====================================================================
// Depthwise causal conv (d_conv=4) + bias + SiLU, on u half of xz.
// One thread per (b,l,e).
// =====================================================================
__global__ __launch_bounds__(256) void conv_silu_kernel(
    const float* __restrict__ cw, const float* __restrict__ cb)
{
    int idx = blockIdx.x * blockDim.x + threadIdx.x;   // over ML*DI
    int e   = idx % DI;
    int bl  = idx / DI;
    int l   = bl % L_;

    float4 w = *(const float4*)(cw + e * 4);
    float wk[4] = {w.x, w.y, w.z, w.w};
    float s = cb[e];
#pragma unroll
    for (int k = 0; k < 4; k++) {
        int ls = l - 3 + k;
        if (ls >= 0)
            s = fmaf(g_xz[(size_t)(bl - 3 + k) * XZW + e], wk[k], s);
    }
    // SiLU
    s = s / (1.f + expf(-s));
    g_u[idx] = s;
}

// =====================================================================
// Selective scan. One thread per (b, e, n). 16 lanes (one n-group) form a
// half-warp; y_t = sum_n h_t*C_t via shfl butterfly over the 16 lanes.
// Writer lane fuses  y = (y + u*Dp) * silu(res).
// =====================================================================
__global__ __launch_bounds__(256) void scan_kernel(
    const float* __restrict__ A_log, const float* __restrict__ Dp)
{
    int gid  = blockIdx.x * blockDim.x + threadIdx.x;
    int pair = gid >> 4;            // (b,e)
    int n    = gid & 15;
    if (pair >= B_ * DI) return;
    int b = pair / DI;
    int e = pair - b * DI;

    const float An = -__expf(A_log[e * DS + n]);
    const float De = Dp[e];
    const bool  writer = (n == 0);

    const float* dt_p  = g_dt  + (size_t)b * L_ * DI + e;
    const float* u_p   = g_u   + (size_t)b * L_ * DI + e;
    const float* ssm_p = g_ssm + (size_t)b * L_ * SSW;
    const float* res_p = g_xz  + (size_t)b * L_ * XZW + DI + e;
    float*       y_p   = g_y   + (size_t)b * L_ * DI + e;

    float h = 0.f;
#pragma unroll 4
    for (int l = 0; l < L_; l++) {
        float dtv = dt_p[(size_t)l * DI];
        float uv  = u_p [(size_t)l * DI];
        float Bv  = ssm_p[(size_t)l * SSW + DR + n];
        float Cv  = ssm_p[(size_t)l * SSW + DR + DS + n];

        float dA = __expf(dtv * An);
        h = fmaf(dA, h, dtv * Bv * uv);

        float p = h * Cv;
        p += __shfl_xor_sync(0xffffffffu, p, 8, 16);
        p += __shfl_xor_sync(0xffffffffu, p, 4, 16);
        p += __shfl_xor_sync(0xffffffffu, p, 2, 16);
        p += __shfl_xor_sync(0xffffffffu, p, 1, 16);

        if (writer) {
            float res = res_p[(size_t)l * XZW];
            float sres = res / (1.f + __expf(-res));
            y_p[(size_t)l * DI] = (p + uv * De) * sres;
        }
    }
}

// =====================================================================
// host launcher
// =====================================================================
extern "C" void kernel_launch(void* const* d_in, const int* in_sizes, int n_in,
                              void* d_out, int out_size)
{
    const float* x     = (const float*)d_in[0];
    const float* W_in  = (const float*)d_in[1];
    const float* convw = (const float*)d_in[2];
    const float* convb = (const float*)d_in[3];
    const float* W_x   = (const float*)d_in[4];
    const float* W_dt  = (const float*)d_in[5];
    const float* b_dt  = (const float*)d_in[6];
    const float* A_log = (const float*)d_in[7];
    const float* Dp    = (const float*)d_in[8];
    const float* W_out = (const float*)d_in[9];
    float* out = (float*)d_out;

    float *xz, *u, *ssm, *dt, *y;
    cudaGetSymbolAddress((void**)&xz,  g_xz);
    cudaGetSymbolAddress((void**)&u,   g_u);
    cudaGetSymbolAddress((void**)&ssm, g_ssm);
    cudaGetSymbolAddress((void**)&dt,  g_dt);
    cudaGetSymbolAddress((void**)&y,   g_y);

    // 1) xz = x @ W_in                       [4096,768]@[768,3072]
    gemm128<<<dim3(XZW / 128, ML / 128), 256>>>(x, W_in, xz, ML, XZW, DM);

    // 2) depthwise causal conv + SiLU -> u
    conv_silu_kernel<<<(ML * DI) / 256, 256>>>(convw, convb);

    // 3) ssm = u @ W_x                       [4096,1536]@[1536,80]
    gemm64<<<dim3((SSW + 63) / 64, ML / 64), 256>>>(
        u, W_x, ssm, ML, SSW, DI, DI, SSW, SSW, nullptr, 0);

    // 4) dt = softplus(ssm[:, :48] @ W_dt + b_dt)   [4096,48]@[48,1536]
    gemm64<<<dim3(DI / 64, ML / 64), 256>>>(
        ssm, W_dt, dt, ML, DI, DR, SSW, DI, DI, b_dt, 1);

    // 5) selective scan + gating -> y
    scan_kernel<<<(B_ * DI * DS) / 256, 256>>>(A_log, Dp);

    // 6) out = y @ W_out                     [4096,1536]@[1536,768]
    gemm128<<<dim3(DM / 128, ML / 128), 256>>>(y, W_out, out, ML, DM, DI);
}

// round 4
// speedup vs baseline: 1.0806x; 1.0806x over previous
#include <cuda_runtime.h>
#include <cuda_bf16.h>
#include <stdint.h>
#include <math.h>

#define B_   2
#define L_   2048
#define DM   768
#define DI   1536
#define DS   16
#define DR   48
#define XZW  (2*DI)        /* 3072 */
#define SSW  (DR + 2*DS)   /* 80   */
#define ML   (B_*L_)       /* 4096 */

// ---------------- scratch (static device globals; no allocation) -------------
__device__ float g_xz [ML * XZW];   // xz = x @ W_in          [4096,3072]
__device__ float g_u  [ML * DI];    // conv+silu output       [4096,1536]
__device__ float g_ssm[ML * SSW];   // u @ W_x                [4096,80]
__device__ float g_dt [ML * DI];    // softplus               [4096,1536]
__device__ float g_y  [ML * DI];    // scan output            [4096,1536]

// bf16 3-split operands (K' = 3K), K-major
__device__ __nv_bfloat16 g_A1[(size_t)ML  * 3 * DM];  // [4096, 2304]
__device__ __nv_bfloat16 g_B1[(size_t)XZW * 3 * DM];  // [3072, 2304]  (W_in^T split)
__device__ __nv_bfloat16 g_A2[(size_t)ML  * 3 * DI];  // [4096, 4608]
__device__ __nv_bfloat16 g_B2[(size_t)DM  * 3 * DI];  // [768,  4608]  (W_out^T split)

__device__ __forceinline__ uint32_t smem_u32(const void* p) {
    uint32_t a;
    asm("{ .reg .u64 t; cvta.to.shared.u64 t, %1; cvt.u32.u64 %0, t; }"
        : "=r"(a) : "l"(p));
    return a;
}

// =====================================================================
// bf16 3-split GEMM via mma.sync (sm_80+ path, works on plain sm_103):
//   C[128 x 128] = A'[row, K3] * B'[col, K3]^T, fp32 accumulate
// 256 threads; warp tile 32x64 (2 m-frags x 8 n-frags of m16n8k16).
// Smem rows padded to 80B -> conflict-free LDS.32 fragment loads.
// 3-stage cp.async pipeline. dyn smem = 3 * 20480 = 61440 B.
// =====================================================================
#define STAGES    3
#define STG_BYTES 20480
#define BOFF      10240
#define GSMEM_BYTES (STAGES * STG_BYTES)

__global__ __launch_bounds__(256) void gemm_mma_3s(
    const __nv_bfloat16* __restrict__ A, const __nv_bfloat16* __restrict__ Bm,
    float* __restrict__ C, int N, int K3)
{
    extern __shared__ char smraw[];
    const uint32_t smb = smem_u32(smraw);
    const int tid  = threadIdx.x;
    const int lane = tid & 31;
    const int wid  = tid >> 5;
    const int wm   = wid >> 1;          // 0..3 : 32-row slice
    const int wn   = wid & 1;           // 0..1 : 64-col slice
    const int row0 = blockIdx.y * 128;
    const int col0 = blockIdx.x * 128;
    const int g    = lane >> 2;         // 0..7
    const int q    = lane & 3;          // 0..3

    // loader mapping: thread t loads 32B (two 16B chunks) of one row per operand
    const int lrow = tid >> 1;                  // 0..127
    const int lcol = (tid & 1) * 2;             // 16B-chunk index (0 or 2)
    const __nv_bfloat16* gA = A  + (size_t)(row0 + lrow) * K3 + lcol * 8;
    const __nv_bfloat16* gB = Bm + (size_t)(col0 + lrow) * K3 + lcol * 8;
    const uint32_t dA = smb + (uint32_t)(lrow * 80 + lcol * 16);
    const uint32_t dB = dA + BOFF;
    const int NT = K3 >> 5;             // k-tiles of 32

    float acc[2][8][4];
#pragma unroll
    for (int mt = 0; mt < 2; mt++)
#pragma unroll
        for (int nt = 0; nt < 8; nt++)
#pragma unroll
            for (int i = 0; i < 4; i++) acc[mt][nt][i] = 0.f;

    auto load_stage = [&](int t, int slot) {
        uint32_t so = (uint32_t)slot * STG_BYTES;
        size_t sa = __cvta_generic_to_global(gA + (size_t)t * 32);
        size_t sb = __cvta_generic_to_global(gB + (size_t)t * 32);
        asm volatile(
            "cp.async.cg.shared.global [%0],[%1],16;\n\t"
            "cp.async.cg.shared.global [%2],[%3],16;\n\t"
            "cp.async.cg.shared.global [%4],[%5],16;\n\t"
            "cp.async.cg.shared.global [%6],[%7],16;\n\t"
            "cp.async.commit_group;"
            :: "r"(dA + so), "l"(sa), "r"(dA + so + 16), "l"(sa + 16),
               "r"(dB + so), "l"(sb), "r"(dB + so + 16), "l"(sb + 16)
            : "memory");
    };

#pragma unroll
    for (int s = 0; s < STAGES; s++)
        if (s < NT) load_stage(s, s);

    for (int t = 0; t < NT; t++) {
        int w = NT - 1 - t; if (w > 2) w = 2;
        if      (w == 0) asm volatile("cp.async.wait_group 0;" ::: "memory");
        else if (w == 1) asm volatile("cp.async.wait_group 1;" ::: "memory");
        else             asm volatile("cp.async.wait_group 2;" ::: "memory");
        __syncthreads();

        const uint32_t sA = smb + (uint32_t)(t % 3) * STG_BYTES;
        const uint32_t sB = sA + BOFF;

#pragma unroll
        for (int kk = 0; kk < 2; kk++) {
            uint32_t a[2][4], b[8][2];
#pragma unroll
            for (int mt = 0; mt < 2; mt++) {
                uint32_t p = sA + (uint32_t)((wm * 32 + mt * 16 + g) * 80 + kk * 32 + q * 4);
                asm("ld.shared.b32 %0,[%1];" : "=r"(a[mt][0]) : "r"(p));
                asm("ld.shared.b32 %0,[%1];" : "=r"(a[mt][1]) : "r"(p + 8 * 80));
                asm("ld.shared.b32 %0,[%1];" : "=r"(a[mt][2]) : "r"(p + 16));
                asm("ld.shared.b32 %0,[%1];" : "=r"(a[mt][3]) : "r"(p + 8 * 80 + 16));
            }
#pragma unroll
            for (int nt = 0; nt < 8; nt++) {
                uint32_t p = sB + (uint32_t)((wn * 64 + nt * 8 + g) * 80 + kk * 32 + q * 4);
                asm("ld.shared.b32 %0,[%1];" : "=r"(b[nt][0]) : "r"(p));
                asm("ld.shared.b32 %0,[%1];" : "=r"(b[nt][1]) : "r"(p + 16));
            }
#pragma unroll
            for (int mt = 0; mt < 2; mt++)
#pragma unroll
                for (int nt = 0; nt < 8; nt++)
                    asm volatile(
                        "mma.sync.aligned.m16n8k16.row.col.f32.bf16.bf16.f32 "
                        "{%0,%1,%2,%3},{%4,%5,%6,%7},{%8,%9},{%0,%1,%2,%3};"
                        : "+f"(acc[mt][nt][0]), "+f"(acc[mt][nt][1]),
                          "+f"(acc[mt][nt][2]), "+f"(acc[mt][nt][3])
                        : "r"(a[mt][0]), "r"(a[mt][1]), "r"(a[mt][2]), "r"(a[mt][3]),
                          "r"(b[nt][0]), "r"(b[nt][1]));
        }
        __syncthreads();
        if (t + STAGES < NT) load_stage(t + STAGES, t % 3);
    }

    // epilogue: fp32 stores straight from accumulators
#pragma unroll
    for (int mt = 0; mt < 2; mt++) {
        int r0 = row0 + wm * 32 + mt * 16 + g;
#pragma unroll
        for (int nt = 0; nt < 8; nt++) {
            int c = col0 + wn * 64 + nt * 8 + q * 2;
            *(float2*)&C[(size_t)r0 * N + c]       = make_float2(acc[mt][nt][0], acc[mt][nt][1]);
            *(float2*)&C[(size_t)(r0 + 8) * N + c] = make_float2(acc[mt][nt][2], acc[mt][nt][3]);
        }
    }
}

// =====================================================================
// fp32 -> bf16 3-split for activations (row-major, no transpose)
// A3[m, 0:K]=hi, [K:2K]=lo, [2K:3K]=hi
// =====================================================================
__global__ __launch_bounds__(256) void convertA(
    const float* __restrict__ A, __nv_bfloat16* __restrict__ A3, int MK2, int K)
{
    int idx = blockIdx.x * blockDim.x + threadIdx.x;
    if (idx >= MK2) return;
    int K2 = K >> 1;
    int m  = idx / K2;
    int kk = idx - m * K2;
    float2 v = ((const float2*)A)[idx];
    __nv_bfloat16 h0 = __float2bfloat16(v.x);
    __nv_bfloat16 h1 = __float2bfloat16(v.y);
    __nv_bfloat16 l0 = __float2bfloat16(v.x - __bfloat162float(h0));
    __nv_bfloat16 l1 = __float2bfloat16(v.y - __bfloat162float(h1));
    __nv_bfloat162 hp; hp.x = h0; hp.y = h1;
    __nv_bfloat162 lp; lp.x = l0; lp.y = l1;
    __nv_bfloat162* out = (__nv_bfloat162*)(A3 + (size_t)m * 3 * K);
    out[kk]          = hp;
    out[kk + K2]     = lp;
    out[kk + 2 * K2] = hp;
}

// =====================================================================
// fp32 weight [K,N] -> transposed bf16 3-split B3[n, 0:K]=hi,[K:2K]=hi,[2K:3K]=lo
// =====================================================================
__global__ __launch_bounds__(256) void convertB_t(
    const float* __restrict__ B, __nv_bfloat16* __restrict__ B3, int K, int N)
{
    __shared__ float t[32][33];
    int n0 = blockIdx.x * 32, k0 = blockIdx.y * 32;
    int tx = threadIdx.x, ty = threadIdx.y;   // 32 x 8
#pragma unroll
    for (int i = 0; i < 32; i += 8)
        t[ty + i][tx] = B[(size_t)(k0 + ty + i) * N + n0 + tx];
    __syncthreads();
#pragma unroll
    for (int i = 0; i < 32; i += 8) {
        int n = n0 + ty + i, k = k0 + tx;
        float v = t[tx][ty + i];
        __nv_bfloat16 h = __float2bfloat16(v);
        __nv_bfloat16 l = __float2bfloat16(v - __bfloat162float(h));
        __nv_bfloat16* o = B3 + (size_t)n * 3 * K + k;
        o[0]     = h;
        o[K]     = h;
        o[2 * K] = l;
    }
}

// =====================================================================
// 64x64x16 fp32 GEMM with strides, N-guards, optional bias + softplus.
// =====================================================================
__global__ __launch_bounds__(256) void gemm64(
    const float* __restrict__ A, const float* __restrict__ Bm,
    float* __restrict__ C, int M, int N, int K,
    int lda, int ldb, int ldc,
    const float* __restrict__ bias, int do_softplus)
{
    __shared__ float As[16][64];
    __shared__ float Bs[16][64];

    const int tid  = threadIdx.x;
    const int tx   = tid & 15;
    const int ty   = tid >> 4;
    const int row0 = blockIdx.y * 64;
    const int col0 = blockIdx.x * 64;

    const int a_row = tid >> 2;
    const int a_k   = (tid & 3) * 4;
    const int b_k   = tid >> 4;
    const int b_c   = (tid & 15) * 4;

    float acc[4][4];
#pragma unroll
    for (int i = 0; i < 4; i++)
#pragma unroll
        for (int j = 0; j < 4; j++) acc[i][j] = 0.f;

    float4 a_ld, b_ld;
    a_ld = *(const float4*)(A + (size_t)(row0 + a_row) * lda + a_k);
    if (col0 + b_c + 4 <= N)
        b_ld = *(const float4*)(Bm + (size_t)b_k * ldb + col0 + b_c);
    else
        b_ld = make_float4(0.f, 0.f, 0.f, 0.f);

    for (int k0 = 16; k0 <= K; k0 += 16) {
        As[a_k + 0][a_row] = a_ld.x;
        As[a_k + 1][a_row] = a_ld.y;
        As[a_k + 2][a_row] = a_ld.z;
        As[a_k + 3][a_row] = a_ld.w;
        *(float4*)&Bs[b_k][b_c] = b_ld;
        __syncthreads();

        if (k0 < K) {
            a_ld = *(const float4*)(A + (size_t)(row0 + a_row) * lda + k0 + a_k);
            if (col0 + b_c + 4 <= N)
                b_ld = *(const float4*)(Bm + (size_t)(k0 + b_k) * ldb + col0 + b_c);
            else
                b_ld = make_float4(0.f, 0.f, 0.f, 0.f);
        }

#pragma unroll
        for (int k = 0; k < 16; k++) {
            float4 a = *(float4*)&As[k][ty * 4];
            float4 b = *(float4*)&Bs[k][tx * 4];
            float av[4] = {a.x, a.y, a.z, a.w};
            float bv[4] = {b.x, b.y, b.z, b.w};
#pragma unroll
            for (int i = 0; i < 4; i++)
#pragma unroll
                for (int j = 0; j < 4; j++)
                    acc[i][j] = fmaf(av[i], bv[j], acc[i][j]);
        }
        __syncthreads();
    }

#pragma unroll
    for (int i = 0; i < 4; i++) {
        int r = row0 + ty * 4 + i;
#pragma unroll
        for (int j = 0; j < 4; j++) {
            int c = col0 + tx * 4 + j;
            if (c < N) {
                float v = acc[i][j];
                if (bias) v += bias[c];
                if (do_softplus) v = (v > 20.f) ? v : log1pf(expf(v));
                C[(size_t)r * ldc + c] = v;
            }
        }
    }
}

// =====================================================================
// Depthwise causal conv (d_conv=4) + bias + SiLU
// =====================================================================
__global__ __launch_bounds__(256) void conv_silu_kernel(
    const float* __restrict__ cw, const float* __restrict__ cb)
{
    int idx = blockIdx.x * blockDim.x + threadIdx.x;
    int e   = idx % DI;
    int bl  = idx / DI;
    int l   = bl % L_;

    float4 w = *(const float4*)(cw + e * 4);
    float wk[4] = {w.x, w.y, w.z, w.w};
    float s = cb[e];
#pragma unroll
    for (int k = 0; k < 4; k++) {
        int ls = l - 3 + k;
        if (ls >= 0)
            s = fmaf(g_xz[(size_t)(bl - 3 + k) * XZW + e], wk[k], s);
    }
    s = s / (1.f + expf(-s));
    g_u[idx] = s;
}

// =====================================================================
// Selective scan (thread per (b,e,n), 16-lane shfl reduce)
// =====================================================================
__global__ __launch_bounds__(256) void scan_kernel(
    const float* __restrict__ A_log, const float* __restrict__ Dp)
{
    int gid  = blockIdx.x * blockDim.x + threadIdx.x;
    int pair = gid >> 4;
    int n    = gid & 15;
    if (pair >= B_ * DI) return;
    int b = pair / DI;
    int e = pair - b * DI;

    const float An = -__expf(A_log[e * DS + n]);
    const float De = Dp[e];
    const bool  writer = (n == 0);

    const float* dt_p  = g_dt  + (size_t)b * L_ * DI + e;
    const float* u_p   = g_u   + (size_t)b * L_ * DI + e;
    const float* ssm_p = g_ssm + (size_t)b * L_ * SSW;
    const float* res_p = g_xz  + (size_t)b * L_ * XZW + DI + e;
    float*       y_p   = g_y   + (size_t)b * L_ * DI + e;

    float h = 0.f;
#pragma unroll 4
    for (int l = 0; l < L_; l++) {
        float dtv = dt_p[(size_t)l * DI];
        float uv  = u_p [(size_t)l * DI];
        float Bv  = ssm_p[(size_t)l * SSW + DR + n];
        float Cv  = ssm_p[(size_t)l * SSW + DR + DS + n];

        float dA = __expf(dtv * An);
        h = fmaf(dA, h, dtv * Bv * uv);

        float p = h * Cv;
        p += __shfl_xor_sync(0xffffffffu, p, 8, 16);
        p += __shfl_xor_sync(0xffffffffu, p, 4, 16);
        p += __shfl_xor_sync(0xffffffffu, p, 2, 16);
        p += __shfl_xor_sync(0xffffffffu, p, 1, 16);

        if (writer) {
            float res = res_p[(size_t)l * XZW];
            float sres = res / (1.f + __expf(-res));
            y_p[(size_t)l * DI] = (p + uv * De) * sres;
        }
    }
}

// =====================================================================
// host launcher
// =====================================================================
extern "C" void kernel_launch(void* const* d_in, const int* in_sizes, int n_in,
                              void* d_out, int out_size)
{
    (void)in_sizes; (void)n_in; (void)out_size;
    const float* x     = (const float*)d_in[0];
    const float* W_in  = (const float*)d_in[1];
    const float* convw = (const float*)d_in[2];
    const float* convb = (const float*)d_in[3];
    const float* W_x   = (const float*)d_in[4];
    const float* W_dt  = (const float*)d_in[5];
    const float* b_dt  = (const float*)d_in[6];
    const float* A_log = (const float*)d_in[7];
    const float* Dp    = (const float*)d_in[8];
    const float* W_out = (const float*)d_in[9];
    float* out = (float*)d_out;

    float *xz, *u, *ssm, *dt, *y;
    cudaGetSymbolAddress((void**)&xz,  g_xz);
    cudaGetSymbolAddress((void**)&u,   g_u);
    cudaGetSymbolAddress((void**)&ssm, g_ssm);
    cudaGetSymbolAddress((void**)&dt,  g_dt);
    cudaGetSymbolAddress((void**)&y,   g_y);
    __nv_bfloat16 *a1, *b1, *a2, *b2;
    cudaGetSymbolAddress((void**)&a1, g_A1);
    cudaGetSymbolAddress((void**)&b1, g_B1);
    cudaGetSymbolAddress((void**)&a2, g_A2);
    cudaGetSymbolAddress((void**)&b2, g_B2);

    cudaFuncSetAttribute(gemm_mma_3s,
        cudaFuncAttributeMaxDynamicSharedMemorySize, GSMEM_BYTES);

    // 1) split/convert operands for GEMM1
    convertB_t<<<dim3(XZW / 32, DM / 32), dim3(32, 8)>>>(W_in, b1, DM, XZW);
    {
        int mk2 = ML * DM / 2;
        convertA<<<(mk2 + 255) / 256, 256>>>(x, a1, mk2, DM);
    }
    // 2) xz = x @ W_in   (tensor cores, 3-split bf16)
    gemm_mma_3s<<<dim3(XZW / 128, ML / 128), 256, GSMEM_BYTES>>>(
        a1, b1, xz, XZW, 3 * DM);

    // 3) depthwise causal conv + SiLU -> u
    conv_silu_kernel<<<(ML * DI) / 256, 256>>>(convw, convb);

    // 4) ssm = u @ W_x
    gemm64<<<dim3((SSW + 63) / 64, ML / 64), 256>>>(
        u, W_x, ssm, ML, SSW, DI, DI, SSW, SSW, nullptr, 0);

    // 5) dt = softplus(ssm[:, :48] @ W_dt + b_dt)
    gemm64<<<dim3(DI / 64, ML / 64), 256>>>(
        ssm, W_dt, dt, ML, DI, DR, SSW, DI, DI, b_dt, 1);

    // 6) selective scan + gating -> y
    scan_kernel<<<(B_ * DI * DS) / 256, 256>>>(A_log, Dp);

    // 7) split/convert operands for GEMM3
    convertB_t<<<dim3(DM / 32, DI / 32), dim3(32, 8)>>>(W_out, b2, DI, DM);
    {
        int mk2 = ML * DI / 2;
        convertA<<<(mk2 + 255) / 256, 256>>>(y, a2, mk2, DI);
    }
    // 8) out = y @ W_out  (tensor cores, 3-split bf16)
    gemm_mma_3s<<<dim3(DM / 128, ML / 128), 256, GSMEM_BYTES>>>(
        a2, b2, out, DM, 3 * DI);
}

// round 5
// speedup vs baseline: 1.5840x; 1.4657x over previous
#include <cuda_runtime.h>
#include <cuda_bf16.h>
#include <stdint.h>
#include <math.h>

#define B_   2
#define L_   2048
#define DM   768
#define DI   1536
#define DS   16
#define DR   48
#define XZW  (2*DI)        /* 3072 */
#define SSW  (DR + 2*DS)   /* 80   */
#define ML   (B_*L_)       /* 4096 */

// ---------------- scratch (static device globals; no allocation) -------------
__device__ float g_xz  [ML * XZW];   // xz = x @ W_in          [4096,3072]
__device__ float g_u   [ML * DI];    // conv+silu output       [4096,1536]
__device__ float g_sres[ML * DI];    // silu(res)              [4096,1536]
__device__ float g_ssm [ML * SSW];   // u @ W_x                [4096,80]
__device__ float g_dt  [ML * DI];    // softplus               [4096,1536]
__device__ float g_y   [ML * DI];    // scan output            [4096,1536]

// bf16 3-split operands (K' = 3K), K-major
__device__ __nv_bfloat16 g_A1[(size_t)ML  * 3 * DM];  // [4096, 2304]
__device__ __nv_bfloat16 g_B1[(size_t)XZW * 3 * DM];  // [3072, 2304]  (W_in^T split)
__device__ __nv_bfloat16 g_A2[(size_t)ML  * 3 * DI];  // [4096, 4608]
__device__ __nv_bfloat16 g_B2[(size_t)DM  * 3 * DI];  // [768,  4608]  (W_out^T split)

__device__ __forceinline__ uint32_t smem_u32(const void* p) {
    uint32_t a;
    asm("{ .reg .u64 t; cvta.to.shared.u64 t, %1; cvt.u32.u64 %0, t; }"
        : "=r"(a) : "l"(p));
    return a;
}

// =====================================================================
// bf16 3-split GEMM via mma.sync m16n8k16 (sm_80+ path):
//   C[128 x 128] = A'[row, K3] * B'[col, K3]^T, fp32 accumulate
// 256 threads, warp tile 32x64. ldmatrix.x4 fragment loads (80B-padded
// rows -> conflict-free). 4-stage cp.async pipeline, 1 sync per k-tile.
// =====================================================================
#define STAGES    4
#define STG_BYTES 20480          /* (128 rows * 80B) * 2 operands */
#define BOFF      10240
#define GSMEM_BYTES (STAGES * STG_BYTES)   /* 81920 */

__global__ __launch_bounds__(256, 2) void gemm_mma_3s(
    const __nv_bfloat16* __restrict__ A, const __nv_bfloat16* __restrict__ Bm,
    float* __restrict__ C, int N, int K3)
{
    extern __shared__ char smraw[];
    const uint32_t smb = smem_u32(smraw);
    const int tid  = threadIdx.x;
    const int lane = tid & 31;
    const int wid  = tid >> 5;
    const int wm   = wid >> 1;          // 0..3 : 32-row slice
    const int wn   = wid & 1;           // 0..1 : 64-col slice
    const int row0 = blockIdx.y * 128;
    const int col0 = blockIdx.x * 128;

    // ---- loader mapping: each thread stages 32B per operand per k-tile ----
    const int lrow = tid >> 1;                   // 0..127
    const __nv_bfloat16* gA = A  + (size_t)(row0 + lrow) * K3 + (tid & 1) * 16;
    const __nv_bfloat16* gB = Bm + (size_t)(col0 + lrow) * K3 + (tid & 1) * 16;
    const uint32_t dA = smb + (uint32_t)(lrow * 80 + (tid & 1) * 32);
    const uint32_t dB = dA + BOFF;
    const int NT = K3 >> 5;                      // k-tiles of 32

    // ---- per-lane ldmatrix addresses (stage-0, kk=0 base) ----
    uint32_t aAddr[2], bAddr[4];
    {
        int r8   = lane & 7;
        int aRow = wm * 32 + ((lane >> 3) & 1) * 8 + r8;
        int aOff = (lane >> 4) * 16;
        aAddr[0] = smb + (uint32_t)(aRow * 80 + aOff);
        aAddr[1] = aAddr[0] + 16u * 80u;
        int bRow = wn * 64 + ((lane >> 4) & 1) * 8 + r8;
        int bOff = ((lane >> 3) & 1) * 16;
#pragma unroll
        for (int p = 0; p < 4; p++)
            bAddr[p] = smb + BOFF + (uint32_t)((bRow + p * 16) * 80 + bOff);
    }

    float acc[2][8][4];
#pragma unroll
    for (int mt = 0; mt < 2; mt++)
#pragma unroll
        for (int nt = 0; nt < 8; nt++)
#pragma unroll
            for (int i = 0; i < 4; i++) acc[mt][nt][i] = 0.f;

    auto load_stage = [&](int t) {
        if (t < NT) {
            uint32_t so = (uint32_t)(t & 3) * STG_BYTES;
            size_t sa = __cvta_generic_to_global(gA + (size_t)t * 32);
            size_t sb = __cvta_generic_to_global(gB + (size_t)t * 32);
            asm volatile(
                "cp.async.cg.shared.global [%0],[%1],16;\n\t"
                "cp.async.cg.shared.global [%2],[%3],16;\n\t"
                "cp.async.cg.shared.global [%4],[%5],16;\n\t"
                "cp.async.cg.shared.global [%6],[%7],16;\n\t"
                "cp.async.commit_group;"
                :: "r"(dA + so), "l"(sa), "r"(dA + so + 16), "l"(sa + 16),
                   "r"(dB + so), "l"(sb), "r"(dB + so + 16), "l"(sb + 16)
                : "memory");
        } else {
            asm volatile("cp.async.commit_group;" ::: "memory");
        }
    };

    load_stage(0); load_stage(1); load_stage(2);

    for (int t = 0; t < NT; t++) {
        asm volatile("cp.async.wait_group 2;" ::: "memory");
        __syncthreads();
        load_stage(t + 3);                       // into slot (t-1)&3, freed by the sync

        const uint32_t so = (uint32_t)(t & 3) * STG_BYTES;
#pragma unroll
        for (int kk = 0; kk < 2; kk++) {
            uint32_t a[2][4], b[4][4];
#pragma unroll
            for (int mt = 0; mt < 2; mt++)
                asm volatile(
                    "ldmatrix.sync.aligned.m8n8.x4.shared.b16 {%0,%1,%2,%3},[%4];"
                    : "=r"(a[mt][0]), "=r"(a[mt][1]), "=r"(a[mt][2]), "=r"(a[mt][3])
                    : "r"(aAddr[mt] + so + kk * 32));
#pragma unroll
            for (int p = 0; p < 4; p++)
                asm volatile(
                    "ldmatrix.sync.aligned.m8n8.x4.shared.b16 {%0,%1,%2,%3},[%4];"
                    : "=r"(b[p][0]), "=r"(b[p][1]), "=r"(b[p][2]), "=r"(b[p][3])
                    : "r"(bAddr[p] + so + kk * 32));
#pragma unroll
            for (int mt = 0; mt < 2; mt++)
#pragma unroll
                for (int nt = 0; nt < 8; nt++)
                    asm volatile(
                        "mma.sync.aligned.m16n8k16.row.col.f32.bf16.bf16.f32 "
                        "{%0,%1,%2,%3},{%4,%5,%6,%7},{%8,%9},{%0,%1,%2,%3};"
                        : "+f"(acc[mt][nt][0]), "+f"(acc[mt][nt][1]),
                          "+f"(acc[mt][nt][2]), "+f"(acc[mt][nt][3])
                        : "r"(a[mt][0]), "r"(a[mt][1]), "r"(a[mt][2]), "r"(a[mt][3]),
                          "r"(b[nt >> 1][(nt & 1) * 2]), "r"(b[nt >> 1][(nt & 1) * 2 + 1]));
        }
    }

    // epilogue: fp32 stores straight from accumulators
    const int g = lane >> 2, q = lane & 3;
#pragma unroll
    for (int mt = 0; mt < 2; mt++) {
        int r0 = row0 + wm * 32 + mt * 16 + g;
#pragma unroll
        for (int nt = 0; nt < 8; nt++) {
            int c = col0 + wn * 64 + nt * 8 + q * 2;
            *(float2*)&C[(size_t)r0 * N + c]       = make_float2(acc[mt][nt][0], acc[mt][nt][1]);
            *(float2*)&C[(size_t)(r0 + 8) * N + c] = make_float2(acc[mt][nt][2], acc[mt][nt][3]);
        }
    }
}

// =====================================================================
// fp32 -> bf16 3-split for activations (row-major, no transpose)
// =====================================================================
__global__ __launch_bounds__(256) void convertA(
    const float* __restrict__ A, __nv_bfloat16* __restrict__ A3, int MK2, int K)
{
    int idx = blockIdx.x * blockDim.x + threadIdx.x;
    if (idx >= MK2) return;
    int K2 = K >> 1;
    int m  = idx / K2;
    int kk = idx - m * K2;
    float2 v = ((const float2*)A)[idx];
    __nv_bfloat16 h0 = __float2bfloat16(v.x);
    __nv_bfloat16 h1 = __float2bfloat16(v.y);
    __nv_bfloat16 l0 = __float2bfloat16(v.x - __bfloat162float(h0));
    __nv_bfloat16 l1 = __float2bfloat16(v.y - __bfloat162float(h1));
    __nv_bfloat162 hp; hp.x = h0; hp.y = h1;
    __nv_bfloat162 lp; lp.x = l0; lp.y = l1;
    __nv_bfloat162* out = (__nv_bfloat162*)(A3 + (size_t)m * 3 * K);
    out[kk]          = hp;
    out[kk + K2]     = lp;
    out[kk + 2 * K2] = hp;
}

// =====================================================================
// fp32 weight [K,N] -> transposed bf16 3-split
// =====================================================================
__global__ __launch_bounds__(256) void convertB_t(
    const float* __restrict__ B, __nv_bfloat16* __restrict__ B3, int K, int N)
{
    __shared__ float t[32][33];
    int n0 = blockIdx.x * 32, k0 = blockIdx.y * 32;
    int tx = threadIdx.x, ty = threadIdx.y;   // 32 x 8
#pragma unroll
    for (int i = 0; i < 32; i += 8)
        t[ty + i][tx] = B[(size_t)(k0 + ty + i) * N + n0 + tx];
    __syncthreads();
#pragma unroll
    for (int i = 0; i < 32; i += 8) {
        int n = n0 + ty + i, k = k0 + tx;
        float v = t[tx][ty + i];
        __nv_bfloat16 h = __float2bfloat16(v);
        __nv_bfloat16 l = __float2bfloat16(v - __bfloat162float(h));
        __nv_bfloat16* o = B3 + (size_t)n * 3 * K + k;
        o[0]     = h;
        o[K]     = h;
        o[2 * K] = l;
    }
}

// =====================================================================
// 64x64x16 fp32 GEMM with strides, N-guards, optional bias + softplus.
// =====================================================================
__global__ __launch_bounds__(256) void gemm64(
    const float* __restrict__ A, const float* __restrict__ Bm,
    float* __restrict__ C, int M, int N, int K,
    int lda, int ldb, int ldc,
    const float* __restrict__ bias, int do_softplus)
{
    __shared__ float As[16][64];
    __shared__ float Bs[16][64];

    const int tid  = threadIdx.x;
    const int tx   = tid & 15;
    const int ty   = tid >> 4;
    const int row0 = blockIdx.y * 64;
    const int col0 = blockIdx.x * 64;

    const int a_row = tid >> 2;
    const int a_k   = (tid & 3) * 4;
    const int b_k   = tid >> 4;
    const int b_c   = (tid & 15) * 4;

    float acc[4][4];
#pragma unroll
    for (int i = 0; i < 4; i++)
#pragma unroll
        for (int j = 0; j < 4; j++) acc[i][j] = 0.f;

    float4 a_ld, b_ld;
    a_ld = *(const float4*)(A + (size_t)(row0 + a_row) * lda + a_k);
    if (col0 + b_c + 4 <= N)
        b_ld = *(const float4*)(Bm + (size_t)b_k * ldb + col0 + b_c);
    else
        b_ld = make_float4(0.f, 0.f, 0.f, 0.f);

    for (int k0 = 16; k0 <= K; k0 += 16) {
        As[a_k + 0][a_row] = a_ld.x;
        As[a_k + 1][a_row] = a_ld.y;
        As[a_k + 2][a_row] = a_ld.z;
        As[a_k + 3][a_row] = a_ld.w;
        *(float4*)&Bs[b_k][b_c] = b_ld;
        __syncthreads();

        if (k0 < K) {
            a_ld = *(const float4*)(A + (size_t)(row0 + a_row) * lda + k0 + a_k);
            if (col0 + b_c + 4 <= N)
                b_ld = *(const float4*)(Bm + (size_t)(k0 + b_k) * ldb + col0 + b_c);
            else
                b_ld = make_float4(0.f, 0.f, 0.f, 0.f);
        }

#pragma unroll
        for (int k = 0; k < 16; k++) {
            float4 a = *(float4*)&As[k][ty * 4];
            float4 b = *(float4*)&Bs[k][tx * 4];
            float av[4] = {a.x, a.y, a.z, a.w};
            float bv[4] = {b.x, b.y, b.z, b.w};
#pragma unroll
            for (int i = 0; i < 4; i++)
#pragma unroll
                for (int j = 0; j < 4; j++)
                    acc[i][j] = fmaf(av[i], bv[j], acc[i][j]);
        }
        __syncthreads();
    }

#pragma unroll
    for (int i = 0; i < 4; i++) {
        int r = row0 + ty * 4 + i;
#pragma unroll
        for (int j = 0; j < 4; j++) {
            int c = col0 + tx * 4 + j;
            if (c < N) {
                float v = acc[i][j];
                if (bias) v += bias[c];
                if (do_softplus) v = (v > 20.f) ? v : log1pf(expf(v));
                C[(size_t)r * ldc + c] = v;
            }
        }
    }
}

// =====================================================================
// Depthwise causal conv (d_conv=4) + bias + SiLU; also precompute silu(res)
// =====================================================================
__global__ __launch_bounds__(256) void conv_silu_kernel(
    const float* __restrict__ cw, const float* __restrict__ cb)
{
    int idx = blockIdx.x * blockDim.x + threadIdx.x;
    int e   = idx % DI;
    int bl  = idx / DI;
    int l   = bl % L_;

    float4 w = *(const float4*)(cw + e * 4);
    float wk[4] = {w.x, w.y, w.z, w.w};
    float s = cb[e];
#pragma unroll
    for (int k = 0; k < 4; k++) {
        int ls = l - 3 + k;
        if (ls >= 0)
            s = fmaf(g_xz[(size_t)(bl - 3 + k) * XZW + e], wk[k], s);
    }
    s = s / (1.f + expf(-s));
    g_u[idx] = s;

    float res = g_xz[(size_t)bl * XZW + DI + e];
    g_sres[idx] = res / (1.f + expf(-res));
}

// =====================================================================
// Selective scan (thread per (b,e,n), 16-lane shfl reduce)
// =====================================================================
__global__ __launch_bounds__(256) void scan_kernel(
    const float* __restrict__ A_log, const float* __restrict__ Dp)
{
    int gid  = blockIdx.x * blockDim.x + threadIdx.x;
    int pair = gid >> 4;
    int n    = gid & 15;
    if (pair >= B_ * DI) return;
    int b = pair / DI;
    int e = pair - b * DI;

    const float An = -__expf(A_log[e * DS + n]);
    const float De = Dp[e];
    const bool  writer = (n == 0);

    const float* dt_p  = g_dt   + (size_t)b * L_ * DI + e;
    const float* u_p   = g_u    + (size_t)b * L_ * DI + e;
    const float* ssm_p = g_ssm  + (size_t)b * L_ * SSW;
    const float* sr_p  = g_sres + (size_t)b * L_ * DI + e;
    float*       y_p   = g_y    + (size_t)b * L_ * DI + e;

    float h = 0.f;
#pragma unroll 4
    for (int l = 0; l < L_; l++) {
        float dtv = dt_p[(size_t)l * DI];
        float uv  = u_p [(size_t)l * DI];
        float Bv  = ssm_p[(size_t)l * SSW + DR + n];
        float Cv  = ssm_p[(size_t)l * SSW + DR + DS + n];

        float dA = __expf(dtv * An);
        h = fmaf(dA, h, dtv * Bv * uv);

        float p = h * Cv;
        p += __shfl_xor_sync(0xffffffffu, p, 8, 16);
        p += __shfl_xor_sync(0xffffffffu, p, 4, 16);
        p += __shfl_xor_sync(0xffffffffu, p, 2, 16);
        p += __shfl_xor_sync(0xffffffffu, p, 1, 16);

        if (writer)
            y_p[(size_t)l * DI] = (p + uv * De) * sr_p[(size_t)l * DI];
    }
}

// =====================================================================
// host launcher
// =====================================================================
extern "C" void kernel_launch(void* const* d_in, const int* in_sizes, int n_in,
                              void* d_out, int out_size)
{
    (void)in_sizes; (void)n_in; (void)out_size;
    const float* x     = (const float*)d_in[0];
    const float* W_in  = (const float*)d_in[1];
    const float* convw = (const float*)d_in[2];
    const float* convb = (const float*)d_in[3];
    const float* W_x   = (const float*)d_in[4];
    const float* W_dt  = (const float*)d_in[5];
    const float* b_dt  = (const float*)d_in[6];
    const float* A_log = (const float*)d_in[7];
    const float* Dp    = (const float*)d_in[8];
    const float* W_out = (const float*)d_in[9];
    float* out = (float*)d_out;

    float *xz, *u, *ssm, *dt, *y;
    cudaGetSymbolAddress((void**)&xz,  g_xz);
    cudaGetSymbolAddress((void**)&u,   g_u);
    cudaGetSymbolAddress((void**)&ssm, g_ssm);
    cudaGetSymbolAddress((void**)&dt,  g_dt);
    cudaGetSymbolAddress((void**)&y,   g_y);
    __nv_bfloat16 *a1, *b1, *a2, *b2;
    cudaGetSymbolAddress((void**)&a1, g_A1);
    cudaGetSymbolAddress((void**)&b1, g_B1);
    cudaGetSymbolAddress((void**)&a2, g_A2);
    cudaGetSymbolAddress((void**)&b2, g_B2);

    cudaFuncSetAttribute(gemm_mma_3s,
        cudaFuncAttributeMaxDynamicSharedMemorySize, GSMEM_BYTES);

    // 1) split/convert operands for GEMM1
    convertB_t<<<dim3(XZW / 32, DM / 32), dim3(32, 8)>>>(W_in, b1, DM, XZW);
    {
        int mk2 = ML * DM / 2;
        convertA<<<(mk2 + 255) / 256, 256>>>(x, a1, mk2, DM);
    }
    // 2) xz = x @ W_in   (tensor cores, 3-split bf16)
    gemm_mma_3s<<<dim3(XZW / 128, ML / 128), 256, GSMEM_BYTES>>>(
        a1, b1, xz, XZW, 3 * DM);

    // 3) depthwise causal conv + SiLU -> u ; silu(res) -> sres
    conv_silu_kernel<<<(ML * DI) / 256, 256>>>(convw, convb);

    // 4) ssm = u @ W_x
    gemm64<<<dim3((SSW + 63) / 64, ML / 64), 256>>>(
        u, W_x, ssm, ML, SSW, DI, DI, SSW, SSW, nullptr, 0);

    // 5) dt = softplus(ssm[:, :48] @ W_dt + b_dt)
    gemm64<<<dim3(DI / 64, ML / 64), 256>>>(
        ssm, W_dt, dt, ML, DI, DR, SSW, DI, DI, b_dt, 1);

    // 6) selective scan + gating -> y
    scan_kernel<<<(B_ * DI * DS) / 256, 256>>>(A_log, Dp);

    // 7) split/convert operands for GEMM3
    convertB_t<<<dim3(DM / 32, DI / 32), dim3(32, 8)>>>(W_out, b2, DI, DM);
    {
        int mk2 = ML * DI / 2;
        convertA<<<(mk2 + 255) / 256, 256>>>(y, a2, mk2, DI);
    }
    // 8) out = y @ W_out  (tensor cores, 3-split bf16)
    gemm_mma_3s<<<dim3(DM / 128, ML / 128), 256, GSMEM_BYTES>>>(
        a2, b2, out, DM, 3 * DI);
}